// round 10
// baseline (speedup 1.0000x reference)
#include <cuda_runtime.h>
#include <math.h>
#include <stdint.h>

#define B_   512
#define NW   64
#define NQ   343
#define NTOK 344
#define DIM  96
#define H    3
#define HD   32
#define NROWS (B_*NTOK)
#define XOUT_SZ ((size_t)B_*NQ*DIM)
#define BMSTR 344

typedef unsigned long long u64;

__device__ float g_att[(size_t)B_*NTOK*DIM];
__device__ float g_bm[(size_t)H*NW*NQ*BMSTR + 16];

// ---------------- kernel 0: bm gather (stride 344, col0 = 0) ----------------
__global__ void bm_pre_kernel(const float* __restrict__ btab,
                              const int* __restrict__ ri,
                              const float* __restrict__ mask) {
    size_t gid = (size_t)blockIdx.x * 256 + threadIdx.x;
    if (gid >= (size_t)H*NW*NQ*BMSTR) return;
    int i  = (int)(gid % (NQ*BMSTR));
    int hw = (int)(gid / (NQ*BMSTR));
    int h = hw / NW, w = hw % NW;
    int r = i / BMSTR, j = i % BMSTR;
    float v = 0.f;
    if (j >= 1)
        v = btab[ri[r*NQ + (j-1)]*H + h] + mask[(size_t)w*NQ*NQ + r*NQ + (j-1)];
    g_bm[gid] = v;
}

// ---------------- f32x2 helpers ----------------
__device__ __forceinline__ u64 pk2(float lo, float hi) {
    u64 r; asm("mov.b64 %0, {%1, %2};" : "=l"(r) : "f"(lo), "f"(hi)); return r;
}
__device__ __forceinline__ void upk2(float& lo, float& hi, u64 v) {
    asm("mov.b64 {%0, %1}, %2;" : "=f"(lo), "=f"(hi) : "l"(v));
}
__device__ __forceinline__ void fma2(u64& d, u64 a, u64 b) {
    asm("fma.rn.f32x2 %0, %1, %2, %3;" : "=l"(d) : "l"(a), "l"(b), "l"(d));
}

// fused smem layout (bytes):
//  phase1: Xs f32 [352][50] @0 (70400) | Wp2 u64 [96][48] @70400 (36864)
//  phase2: P u64 per-warp @0 (46464) | Qs @56960 | Kt @104832 | Vs @150400
//  bis f32[96] @201088  (never aliased)
#define SM_QS   56960
#define SM_KT   104832
#define SM_VS   150400
#define SM_WP2  70400
#define SM_BIS  201088
#define FUSED_SMEM 201472

__global__ void __launch_bounds__(704, 1)
fused_attn_kernel(const float* __restrict__ x,
                  const float* __restrict__ gt,
                  const float* __restrict__ Wqkv,
                  const float* __restrict__ bqkv) {
    extern __shared__ char smem[];
    float* Xs  = (float*)smem;                 // [352][50]
    u64*   Wp2 = (u64*)(smem + SM_WP2);        // [96][48]
    float* bis = (float*)(smem + SM_BIS);      // [96]
    float* Qs  = (float*)(smem + SM_QS);       // [176 pairs][68]
    float* Kt  = (float*)(smem + SM_KT);       // [32][356]
    float* Vs  = (float*)(smem + SM_VS);       // [352][36]

    const int bid = blockIdx.x;
    const int rep = bid & 7;
    const int hw  = bid >> 3;
    const int w   = hw & 63;
    const int h   = hw >> 6;
    const int b   = (rep << 6) + w;

    const int tid  = threadIdx.x;
    const int wid  = tid >> 5;
    const int lane = tid & 31;
    const int rg   = lane >> 3;     // 4 row-groups of 4 rows
    const int cg   = lane & 7;      // 8 col-groups of 6 colpairs
    const float scale = 0.17677669529663687f;
    const int mb = wid * 16;

    // ---- fill Wp2 (once) + bias ----
    for (int idx = tid; idx < 96*48; idx += 704) {
        int k = idx / 48, cp = idx % 48;
        int ce = 2*cp, co = ce + 1;
        int re = (ce < 32) ? (h*HD + ce)
               : (ce < 64) ? (DIM + h*HD + (ce-32))
                           : (2*DIM + h*HD + (ce-64));
        int ro = (co < 32) ? (h*HD + co)
               : (co < 64) ? (DIM + h*HD + (co-32))
                           : (2*DIM + h*HD + (co-64));
        Wp2[idx] = pk2(Wqkv[(size_t)re*DIM + k], Wqkv[(size_t)ro*DIM + k]);
    }
    if (tid < 96) {
        int c = tid;
        int row = (c < 32) ? (h*HD + c)
                : (c < 64) ? (DIM + h*HD + (c-32))
                           : (2*DIM + h*HD + (c-64));
        bis[c] = bqkv[row];
    }

    // ---- phase 1: f32x2 GEMM, 2 passes of 48 k ----
    u64 a2[4][6];
    #pragma unroll
    for (int i = 0; i < 4; ++i)
        #pragma unroll
        for (int j = 0; j < 6; ++j) a2[i][j] = pk2(0.f, 0.f);

    for (int pass = 0; pass < 2; ++pass) {
        if (pass) __syncthreads();
        for (int idx = tid; idx < 352*24; idx += 704) {
            int n = idx / 24, c2 = idx % 24;
            float2 v2 = make_float2(0.f, 0.f);
            if (n < NTOK) {
                const float* src = (n == 0) ? (gt + (size_t)b*DIM)
                                            : (x + ((size_t)b*NQ + (n-1))*DIM);
                v2 = *(const float2*)(src + pass*48 + 2*c2);
            }
            *(float2*)&Xs[n*50 + 2*c2] = v2;
        }
        __syncthreads();

        const float* xrow = Xs + (mb + rg*4)*50;
        const u64*   wrow = Wp2 + (size_t)pass*48*48 + cg*6;
        #pragma unroll 4
        for (int k = 0; k < 48; ++k) {
            u64 x2[4];
            #pragma unroll
            for (int i = 0; i < 4; ++i) {
                float xv = xrow[i*50 + k];
                x2[i] = pk2(xv, xv);
            }
            ulonglong2 wa = *(const ulonglong2*)(wrow + (size_t)k*48);
            ulonglong2 wb = *(const ulonglong2*)(wrow + (size_t)k*48 + 2);
            ulonglong2 wc = *(const ulonglong2*)(wrow + (size_t)k*48 + 4);
            u64 wv[6] = {wa.x, wa.y, wb.x, wb.y, wc.x, wc.y};
            #pragma unroll
            for (int i = 0; i < 4; ++i)
                #pragma unroll
                for (int j = 0; j < 6; ++j)
                    fma2(a2[i][j], x2[i], wv[j]);
        }
    }
    __syncthreads();

    // ---- phase-1 epilogue: scatter to Qs / Kt / Vs ----
    #pragma unroll
    for (int i = 0; i < 4; ++i) {
        int n = mb + rg*4 + i;
        #pragma unroll
        for (int j = 0; j < 6; ++j) {
            float ve, vo;
            upk2(ve, vo, a2[i][j]);
            int ce = (cg*6 + j)*2;
            ve += bis[ce];
            vo += bis[ce+1];
            int sec = ce >> 5, d = ce & 31;
            if (sec == 0) {
                Qs[(n>>1)*68 + d*2     + (n&1)] = ve*scale;
                Qs[(n>>1)*68 + (d+1)*2 + (n&1)] = vo*scale;
            } else if (sec == 1) {
                Kt[d*356 + n]     = ve;
                Kt[(d+1)*356 + n] = vo;
            } else {
                Vs[n*36 + d]     = ve;
                Vs[n*36 + d + 1] = vo;
            }
        }
    }
    __syncthreads();

    // ---- phase 2: f32x2 attention (unchanged from R9) ----
    const int tq = lane >> 3;
    const int tk = lane & 7;
    u64* Pw = (u64*)(smem + wid*2112);
    const float* bmb = g_bm + ((size_t)(h*NW + w)) * NQ * BMSTR;
    const int q0 = mb + tq*4;
    const int pr0 = tq*2;

    u64 o2[2][4];
    float l4[4] = {0.f, 0.f, 0.f, 0.f};
    #pragma unroll
    for (int p = 0; p < 2; ++p)
        #pragma unroll
        for (int c = 0; c < 4; ++c) o2[p][c] = pk2(0.f, 0.f);

    for (int kb = 0; kb < 11; ++kb) {
        const int kbase = kb*32;

        u64 acc2[2][4];
        #pragma unroll
        for (int p = 0; p < 2; ++p)
            #pragma unroll
            for (int c = 0; c < 4; ++c) acc2[p][c] = pk2(0.f, 0.f);

        const float* kp = Kt + kbase + tk*4;
        const float* qp = Qs + (q0>>1)*68;
        #pragma unroll 8
        for (int d = 0; d < 32; ++d) {
            u64 qa = *(const u64*)(qp + 2*d);
            u64 qb = *(const u64*)(qp + 68 + 2*d);
            float4 kv = *(const float4*)(kp + d*356);
            u64 k20 = pk2(kv.x, kv.x), k21 = pk2(kv.y, kv.y);
            u64 k22 = pk2(kv.z, kv.z), k23 = pk2(kv.w, kv.w);
            fma2(acc2[0][0], qa, k20); fma2(acc2[0][1], qa, k21);
            fma2(acc2[0][2], qa, k22); fma2(acc2[0][3], qa, k23);
            fma2(acc2[1][0], qb, k20); fma2(acc2[1][1], qb, k21);
            fma2(acc2[1][2], qb, k22); fma2(acc2[1][3], qb, k23);
        }

        #pragma unroll
        for (int p = 0; p < 2; ++p) {
            int re = q0 + 2*p, ro = re + 1;
            bool ve = (re >= 1) && (re < NTOK);
            bool vo = (ro < NTOK);
            float4 bme = ve ? __ldg((const float4*)(bmb + (size_t)(re-1)*BMSTR + kbase + tk*4))
                            : make_float4(0.f,0.f,0.f,0.f);
            float4 bmo = vo ? __ldg((const float4*)(bmb + (size_t)(ro-1)*BMSTR + kbase + tk*4))
                            : make_float4(0.f,0.f,0.f,0.f);
            float be[4] = {bme.x, bme.y, bme.z, bme.w};
            float bo[4] = {bmo.x, bmo.y, bmo.z, bmo.w};
            #pragma unroll
            for (int c = 0; c < 4; ++c) {
                float se, so;
                upk2(se, so, acc2[p][c]);
                int j = kbase + tk*4 + c;
                float pe = (j < NTOK) ? __expf(se + be[c]) : 0.f;
                float po = (j < NTOK) ? __expf(so + bo[c]) : 0.f;
                l4[2*p]   += pe;
                l4[2*p+1] += po;
                Pw[(pr0 + p)*33 + tk*4 + c] = pk2(pe, po);
            }
        }
        __syncwarp();

        const float* vp = Vs + (size_t)kbase*36 + tk*4;
        #pragma unroll 8
        for (int j = 0; j < 32; ++j) {
            u64 p20 = Pw[pr0*33 + j];
            u64 p21 = Pw[(pr0+1)*33 + j];
            float4 vv = *(const float4*)(vp + j*36);
            u64 v20 = pk2(vv.x, vv.x), v21 = pk2(vv.y, vv.y);
            u64 v22 = pk2(vv.z, vv.z), v23 = pk2(vv.w, vv.w);
            fma2(o2[0][0], p20, v20); fma2(o2[0][1], p20, v21);
            fma2(o2[0][2], p20, v22); fma2(o2[0][3], p20, v23);
            fma2(o2[1][0], p21, v20); fma2(o2[1][1], p21, v21);
            fma2(o2[1][2], p21, v22); fma2(o2[1][3], p21, v23);
        }
        __syncwarp();
    }

    #pragma unroll
    for (int a = 0; a < 4; ++a) {
        l4[a] += __shfl_xor_sync(0xffffffffu, l4[a], 1);
        l4[a] += __shfl_xor_sync(0xffffffffu, l4[a], 2);
        l4[a] += __shfl_xor_sync(0xffffffffu, l4[a], 4);
    }
    #pragma unroll
    for (int p = 0; p < 2; ++p) {
        float oe[4], oo[4];
        #pragma unroll
        for (int c = 0; c < 4; ++c) upk2(oe[c], oo[c], o2[p][c]);
        int re = q0 + 2*p, ro = re + 1;
        if (re < NTOK) {
            float inv = 1.f / l4[2*p];
            *(float4*)(g_att + ((size_t)b*NTOK + re)*DIM + h*HD + tk*4) =
                make_float4(oe[0]*inv, oe[1]*inv, oe[2]*inv, oe[3]*inv);
        }
        if (ro < NTOK) {
            float inv = 1.f / l4[2*p+1];
            *(float4*)(g_att + ((size_t)b*NTOK + ro)*DIM + h*HD + tk*4) =
                make_float4(oo[0]*inv, oo[1]*inv, oo[2]*inv, oo[3]*inv);
        }
    }
}

// ---------------- proj: f32x2 GEMM + scatter ----------------
#define PROJ_SMEM (25600 + 36864)   // Asm f32[64][100] + Wp2 u64[96][48]
__global__ void __launch_bounds__(256, 3)
proj_kernel(const float* __restrict__ W,
            const float* __restrict__ bp,
            float* __restrict__ dout) {
    extern __shared__ char sm[];
    float* Asm = (float*)sm;                // [64][100]
    u64*   Wp2 = (u64*)(sm + 25600);        // [96][48]
    const int tid  = threadIdx.x;
    const int row0 = blockIdx.x * 64;
    const int rg = tid >> 4;    // 16 row-groups of 4
    const int cg = tid & 15;    // 16 col-groups of 3 colpairs

    for (int idx = tid; idx < 64*24; idx += 256) {
        int r = idx / 24, c4 = idx % 24;
        *(float4*)&Asm[r*100 + c4*4] =
            *(const float4*)(g_att + (size_t)(row0 + r)*DIM + c4*4);
    }
    for (int idx = tid; idx < 96*48; idx += 256) {
        int k = idx / 48, cp = idx % 48;
        Wp2[idx] = pk2(W[(size_t)(2*cp)*DIM + k], W[(size_t)(2*cp+1)*DIM + k]);
    }
    __syncthreads();

    u64 a2[4][3];
    #pragma unroll
    for (int i = 0; i < 4; ++i)
        #pragma unroll
        for (int j = 0; j < 3; ++j) a2[i][j] = pk2(0.f, 0.f);

    const float* xrow = Asm + rg*4*100;
    const u64*   wrow = Wp2 + cg*3;
    #pragma unroll 4
    for (int k = 0; k < 96; ++k) {
        u64 x2[4];
        #pragma unroll
        for (int i = 0; i < 4; ++i) {
            float xv = xrow[i*100 + k];
            x2[i] = pk2(xv, xv);
        }
        u64 w0 = wrow[(size_t)k*48];
        u64 w1 = wrow[(size_t)k*48 + 1];
        u64 w2 = wrow[(size_t)k*48 + 2];
        #pragma unroll
        for (int i = 0; i < 4; ++i) {
            fma2(a2[i][0], x2[i], w0);
            fma2(a2[i][1], x2[i], w1);
            fma2(a2[i][2], x2[i], w2);
        }
    }

    #pragma unroll
    for (int i = 0; i < 4; ++i) {
        int gr = row0 + rg*4 + i;
        int b = gr / NTOK, n = gr % NTOK;
        #pragma unroll
        for (int j = 0; j < 3; ++j) {
            float ve, vo;
            upk2(ve, vo, a2[i][j]);
            int ce = (cg*3 + j)*2;
            ve += __ldg(bp + ce);
            vo += __ldg(bp + ce + 1);
            if (n == 0) {
                dout[XOUT_SZ + (size_t)b*DIM + ce]     = ve;
                dout[XOUT_SZ + (size_t)b*DIM + ce + 1] = vo;
            } else {
                dout[((size_t)b*NQ + (n-1))*DIM + ce]     = ve;
                dout[((size_t)b*NQ + (n-1))*DIM + ce + 1] = vo;
            }
        }
    }
}

// ---------------- launch ----------------
extern "C" void kernel_launch(void* const* d_in, const int* in_sizes, int n_in,
                              void* d_out, int out_size) {
    const float* x     = (const float*)d_in[0];
    const float* gt    = (const float*)d_in[1];
    const float* mask  = (const float*)d_in[2];
    const int*   ri    = (const int*)  d_in[3];
    const float* Wqkv  = (const float*)d_in[4];
    const float* bqkv  = (const float*)d_in[5];
    const float* Wproj = (const float*)d_in[6];
    const float* bproj = (const float*)d_in[7];
    const float* btab  = (const float*)d_in[8];
    float* out = (float*)d_out;

    cudaFuncSetAttribute(fused_attn_kernel, cudaFuncAttributeMaxDynamicSharedMemorySize, FUSED_SMEM);
    cudaFuncSetAttribute(proj_kernel,       cudaFuncAttributeMaxDynamicSharedMemorySize, PROJ_SMEM);

    {
        size_t total = (size_t)H*NW*NQ*BMSTR;
        bm_pre_kernel<<<(unsigned)((total + 255)/256), 256>>>(btab, ri, mask);
    }
    fused_attn_kernel<<<B_*H, 704, FUSED_SMEM>>>(x, gt, Wqkv, bqkv);
    proj_kernel<<<NROWS/64, 256, PROJ_SMEM>>>(Wproj, bproj, out);
}

// round 11
// speedup vs baseline: 1.0477x; 1.0477x over previous
#include <cuda_runtime.h>
#include <math.h>
#include <stdint.h>

#define B_   512
#define NW   64
#define NQ   343
#define NTOK 344
#define DIM  96
#define H    3
#define HD   32
#define NROWS (B_*NTOK)
#define XOUT_SZ ((size_t)B_*NQ*DIM)
#define BMSTR 344

typedef unsigned long long u64;

__device__ float g_att[(size_t)B_*NTOK*DIM];
__device__ float g_bm[(size_t)H*NW*NQ*BMSTR + 16];

// ---------------- kernel 0: bm gather (stride 344, col0 = 0) ----------------
__global__ void bm_pre_kernel(const float* __restrict__ btab,
                              const int* __restrict__ ri,
                              const float* __restrict__ mask) {
    size_t gid = (size_t)blockIdx.x * 256 + threadIdx.x;
    if (gid >= (size_t)H*NW*NQ*BMSTR) return;
    int i  = (int)(gid % (NQ*BMSTR));
    int hw = (int)(gid / (NQ*BMSTR));
    int h = hw / NW, w = hw % NW;
    int r = i / BMSTR, j = i % BMSTR;
    float v = 0.f;
    if (j >= 1)
        v = btab[ri[r*NQ + (j-1)]*H + h] + mask[(size_t)w*NQ*NQ + r*NQ + (j-1)];
    g_bm[gid] = v;
}

// ---------------- f32x2 helpers ----------------
__device__ __forceinline__ u64 pk2(float lo, float hi) {
    u64 r; asm("mov.b64 %0, {%1, %2};" : "=l"(r) : "f"(lo), "f"(hi)); return r;
}
__device__ __forceinline__ void upk2(float& lo, float& hi, u64 v) {
    asm("mov.b64 {%0, %1}, %2;" : "=f"(lo), "=f"(hi) : "l"(v));
}
__device__ __forceinline__ void fma2(u64& d, u64 a, u64 b) {
    asm("fma.rn.f32x2 %0, %1, %2, %3;" : "=l"(d) : "l"(a), "l"(b), "l"(d));
}

// fused smem (bytes):
//  phase1 (aliased, dead after epilogue sync):
//    Xs f32[352][98] @0 (137984) | Wp2 u64[96][48] @137984 (36864)
//  phase2: P u64 per-warp @wid*2112 [0,46464) | Qs @56960 | Kt @104832 | Vs @150400
//  bis f32[96] @201088 (never aliased)
#define SM_QS   56960
#define SM_KT   104832
#define SM_VS   150400
#define SM_WP2  137984
#define SM_BIS  201088
#define FUSED_SMEM 201472

__global__ void __launch_bounds__(704, 1)
fused_attn_kernel(const float* __restrict__ x,
                  const float* __restrict__ gt,
                  const float* __restrict__ Wqkv,
                  const float* __restrict__ bqkv) {
    extern __shared__ char smem[];
    float* Xs  = (float*)smem;                 // [352][98]
    u64*   Wp2 = (u64*)(smem + SM_WP2);        // [96][48]
    float* bis = (float*)(smem + SM_BIS);      // [96]
    float* Qs  = (float*)(smem + SM_QS);       // [176 pairs][68]
    float* Kt  = (float*)(smem + SM_KT);       // [32][356]
    float* Vs  = (float*)(smem + SM_VS);       // [352][36]

    const int bid = blockIdx.x;
    const int rep = bid & 7;
    const int hw  = bid >> 3;
    const int w   = hw & 63;
    const int h   = hw >> 6;
    const int b   = (rep << 6) + w;

    const int tid  = threadIdx.x;
    const int wid  = tid >> 5;
    const int lane = tid & 31;
    const int rg   = lane >> 3;     // 4 row-groups of 4 rows
    const int cg   = lane & 7;      // 8 col-groups of 6 colpairs
    const float scale = 0.17677669529663687f;
    const int mb = wid * 16;

    // ---- fills: X (all 96 k), Wp2, bias ----
    for (int idx = tid; idx < 352*48; idx += 704) {
        int n = idx / 48, c2 = idx % 48;
        float2 v2 = make_float2(0.f, 0.f);
        if (n < NTOK) {
            const float* src = (n == 0) ? (gt + (size_t)b*DIM)
                                        : (x + ((size_t)b*NQ + (n-1))*DIM);
            v2 = *(const float2*)(src + 2*c2);
        }
        *(float2*)&Xs[n*98 + 2*c2] = v2;
    }
    for (int idx = tid; idx < 96*48; idx += 704) {
        int k = idx / 48, cp = idx % 48;
        int ce = 2*cp, co = ce + 1;
        int re = (ce < 32) ? (h*HD + ce)
               : (ce < 64) ? (DIM + h*HD + (ce-32))
                           : (2*DIM + h*HD + (ce-64));
        int ro = (co < 32) ? (h*HD + co)
               : (co < 64) ? (DIM + h*HD + (co-32))
                           : (2*DIM + h*HD + (co-64));
        Wp2[idx] = pk2(Wqkv[(size_t)re*DIM + k], Wqkv[(size_t)ro*DIM + k]);
    }
    if (tid < 96) {
        int c = tid;
        int row = (c < 32) ? (h*HD + c)
                : (c < 64) ? (DIM + h*HD + (c-32))
                           : (2*DIM + h*HD + (c-64));
        bis[c] = bqkv[row];
    }
    __syncthreads();

    // ---- phase 1: single-pass f32x2 GEMM ----
    u64 a2[4][6];
    #pragma unroll
    for (int i = 0; i < 4; ++i)
        #pragma unroll
        for (int j = 0; j < 6; ++j) a2[i][j] = pk2(0.f, 0.f);

    {
        const float* xrow = Xs + (mb + rg*4)*98;
        const u64*   wrow = Wp2 + cg*6;
        #pragma unroll 4
        for (int k = 0; k < 96; ++k) {
            u64 x2[4];
            #pragma unroll
            for (int i = 0; i < 4; ++i) {
                float xv = xrow[i*98 + k];
                x2[i] = pk2(xv, xv);
            }
            ulonglong2 wa = *(const ulonglong2*)(wrow + (size_t)k*48);
            ulonglong2 wb = *(const ulonglong2*)(wrow + (size_t)k*48 + 2);
            ulonglong2 wc = *(const ulonglong2*)(wrow + (size_t)k*48 + 4);
            u64 wv[6] = {wa.x, wa.y, wb.x, wb.y, wc.x, wc.y};
            #pragma unroll
            for (int i = 0; i < 4; ++i)
                #pragma unroll
                for (int j = 0; j < 6; ++j)
                    fma2(a2[i][j], x2[i], wv[j]);
        }
    }
    __syncthreads();   // all phase-1 reads done before epilogue overwrites aliases

    // ---- epilogue: scatter to Qs / Kt / Vs ----
    #pragma unroll
    for (int i = 0; i < 4; ++i) {
        int n = mb + rg*4 + i;
        #pragma unroll
        for (int j = 0; j < 6; ++j) {
            float ve, vo;
            upk2(ve, vo, a2[i][j]);
            int ce = (cg*6 + j)*2;
            ve += bis[ce];
            vo += bis[ce+1];
            int sec = ce >> 5, d = ce & 31;
            if (sec == 0) {
                Qs[(n>>1)*68 + d*2     + (n&1)] = ve*scale;
                Qs[(n>>1)*68 + (d+1)*2 + (n&1)] = vo*scale;
            } else if (sec == 1) {
                Kt[d*356 + n]     = ve;
                Kt[(d+1)*356 + n] = vo;
            } else {
                Vs[n*36 + d]     = ve;
                Vs[n*36 + d + 1] = vo;
            }
        }
    }
    __syncthreads();

    // ---- phase 2: f32x2 attention (identical to R9) ----
    const int tq = lane >> 3;
    const int tk = lane & 7;
    u64* Pw = (u64*)(smem + wid*2112);
    const float* bmb = g_bm + ((size_t)(h*NW + w)) * NQ * BMSTR;
    const int q0 = mb + tq*4;
    const int pr0 = tq*2;

    u64 o2[2][4];
    float l4[4] = {0.f, 0.f, 0.f, 0.f};
    #pragma unroll
    for (int p = 0; p < 2; ++p)
        #pragma unroll
        for (int c = 0; c < 4; ++c) o2[p][c] = pk2(0.f, 0.f);

    for (int kb = 0; kb < 11; ++kb) {
        const int kbase = kb*32;

        u64 acc2[2][4];
        #pragma unroll
        for (int p = 0; p < 2; ++p)
            #pragma unroll
            for (int c = 0; c < 4; ++c) acc2[p][c] = pk2(0.f, 0.f);

        const float* kp = Kt + kbase + tk*4;
        const float* qp = Qs + (q0>>1)*68;
        #pragma unroll 8
        for (int d = 0; d < 32; ++d) {
            u64 qa = *(const u64*)(qp + 2*d);
            u64 qb = *(const u64*)(qp + 68 + 2*d);
            float4 kv = *(const float4*)(kp + d*356);
            u64 k20 = pk2(kv.x, kv.x), k21 = pk2(kv.y, kv.y);
            u64 k22 = pk2(kv.z, kv.z), k23 = pk2(kv.w, kv.w);
            fma2(acc2[0][0], qa, k20); fma2(acc2[0][1], qa, k21);
            fma2(acc2[0][2], qa, k22); fma2(acc2[0][3], qa, k23);
            fma2(acc2[1][0], qb, k20); fma2(acc2[1][1], qb, k21);
            fma2(acc2[1][2], qb, k22); fma2(acc2[1][3], qb, k23);
        }

        #pragma unroll
        for (int p = 0; p < 2; ++p) {
            int re = q0 + 2*p, ro = re + 1;
            bool ve = (re >= 1) && (re < NTOK);
            bool vo = (ro < NTOK);
            float4 bme = ve ? __ldg((const float4*)(bmb + (size_t)(re-1)*BMSTR + kbase + tk*4))
                            : make_float4(0.f,0.f,0.f,0.f);
            float4 bmo = vo ? __ldg((const float4*)(bmb + (size_t)(ro-1)*BMSTR + kbase + tk*4))
                            : make_float4(0.f,0.f,0.f,0.f);
            float be[4] = {bme.x, bme.y, bme.z, bme.w};
            float bo[4] = {bmo.x, bmo.y, bmo.z, bmo.w};
            #pragma unroll
            for (int c = 0; c < 4; ++c) {
                float se, so;
                upk2(se, so, acc2[p][c]);
                int j = kbase + tk*4 + c;
                float pe = (j < NTOK) ? __expf(se + be[c]) : 0.f;
                float po = (j < NTOK) ? __expf(so + bo[c]) : 0.f;
                l4[2*p]   += pe;
                l4[2*p+1] += po;
                Pw[(pr0 + p)*33 + tk*4 + c] = pk2(pe, po);
            }
        }
        __syncwarp();

        const float* vp = Vs + (size_t)kbase*36 + tk*4;
        #pragma unroll 8
        for (int j = 0; j < 32; ++j) {
            u64 p20 = Pw[pr0*33 + j];
            u64 p21 = Pw[(pr0+1)*33 + j];
            float4 vv = *(const float4*)(vp + j*36);
            u64 v20 = pk2(vv.x, vv.x), v21 = pk2(vv.y, vv.y);
            u64 v22 = pk2(vv.z, vv.z), v23 = pk2(vv.w, vv.w);
            fma2(o2[0][0], p20, v20); fma2(o2[0][1], p20, v21);
            fma2(o2[0][2], p20, v22); fma2(o2[0][3], p20, v23);
            fma2(o2[1][0], p21, v20); fma2(o2[1][1], p21, v21);
            fma2(o2[1][2], p21, v22); fma2(o2[1][3], p21, v23);
        }
        __syncwarp();
    }

    #pragma unroll
    for (int a = 0; a < 4; ++a) {
        l4[a] += __shfl_xor_sync(0xffffffffu, l4[a], 1);
        l4[a] += __shfl_xor_sync(0xffffffffu, l4[a], 2);
        l4[a] += __shfl_xor_sync(0xffffffffu, l4[a], 4);
    }
    #pragma unroll
    for (int p = 0; p < 2; ++p) {
        float oe[4], oo[4];
        #pragma unroll
        for (int c = 0; c < 4; ++c) upk2(oe[c], oo[c], o2[p][c]);
        int re = q0 + 2*p, ro = re + 1;
        if (re < NTOK) {
            float inv = 1.f / l4[2*p];
            *(float4*)(g_att + ((size_t)b*NTOK + re)*DIM + h*HD + tk*4) =
                make_float4(oe[0]*inv, oe[1]*inv, oe[2]*inv, oe[3]*inv);
        }
        if (ro < NTOK) {
            float inv = 1.f / l4[2*p+1];
            *(float4*)(g_att + ((size_t)b*NTOK + ro)*DIM + h*HD + tk*4) =
                make_float4(oo[0]*inv, oo[1]*inv, oo[2]*inv, oo[3]*inv);
        }
    }
}

// ---------------- proj: R9's proven version (unchanged) ----------------
#define GEMM_SMEM ((128*100 + 96*100) * 4)
__global__ void __launch_bounds__(256, 2)
proj_kernel(const float* __restrict__ W,
            const float* __restrict__ bp,
            float* __restrict__ dout) {
    extern __shared__ float sm[];
    float* Asm = sm;
    float* Wsm = sm + 128*100;
    const int tid  = threadIdx.x;
    const int row0 = blockIdx.x * 128;

    for (int idx = tid; idx < 128*24; idx += 256) {
        int r = idx / 24, c4 = idx % 24;
        *(float4*)&Asm[r*100 + c4*4] =
            *(const float4*)(g_att + (size_t)(row0 + r)*DIM + c4*4);
    }
    for (int idx = tid; idx < 96*24; idx += 256) {
        int r = idx / 24, c4 = idx % 24;
        *(float4*)&Wsm[r*100 + c4*4] = *(const float4*)(W + (size_t)r*96 + c4*4);
    }
    __syncthreads();

    const int tx = tid % 16;
    const int ty = tid / 16;
    float acc[8][6];
    #pragma unroll
    for (int i = 0; i < 8; ++i)
        #pragma unroll
        for (int j = 0; j < 6; ++j) acc[i][j] = 0.f;

    #pragma unroll 2
    for (int k = 0; k < 96; k += 4) {
        float4 a4[8], w4[6];
        #pragma unroll
        for (int i = 0; i < 8; ++i) a4[i] = *(const float4*)&Asm[(ty*8+i)*100 + k];
        #pragma unroll
        for (int j = 0; j < 6; ++j) w4[j] = *(const float4*)&Wsm[(tx*6+j)*100 + k];
        #pragma unroll
        for (int i = 0; i < 8; ++i)
            #pragma unroll
            for (int j = 0; j < 6; ++j)
                acc[i][j] += a4[i].x*w4[j].x + a4[i].y*w4[j].y
                           + a4[i].z*w4[j].z + a4[i].w*w4[j].w;
    }

    #pragma unroll
    for (int i = 0; i < 8; ++i) {
        int gr = row0 + ty*8 + i;
        int b = gr / NTOK, n = gr % NTOK;
        #pragma unroll
        for (int j = 0; j < 6; ++j) {
            int c = tx*6 + j;
            float v = acc[i][j] + bp[c];
            if (n == 0) dout[XOUT_SZ + (size_t)b*DIM + c] = v;
            else        dout[((size_t)b*NQ + (n-1))*DIM + c] = v;
        }
    }
}

// ---------------- launch ----------------
extern "C" void kernel_launch(void* const* d_in, const int* in_sizes, int n_in,
                              void* d_out, int out_size) {
    const float* x     = (const float*)d_in[0];
    const float* gt    = (const float*)d_in[1];
    const float* mask  = (const float*)d_in[2];
    const int*   ri    = (const int*)  d_in[3];
    const float* Wqkv  = (const float*)d_in[4];
    const float* bqkv  = (const float*)d_in[5];
    const float* Wproj = (const float*)d_in[6];
    const float* bproj = (const float*)d_in[7];
    const float* btab  = (const float*)d_in[8];
    float* out = (float*)d_out;

    cudaFuncSetAttribute(fused_attn_kernel, cudaFuncAttributeMaxDynamicSharedMemorySize, FUSED_SMEM);
    cudaFuncSetAttribute(proj_kernel,       cudaFuncAttributeMaxDynamicSharedMemorySize, GEMM_SMEM);

    {
        size_t total = (size_t)H*NW*NQ*BMSTR;
        bm_pre_kernel<<<(unsigned)((total + 255)/256), 256>>>(btab, ri, mask);
    }
    fused_attn_kernel<<<B_*H, 704, FUSED_SMEM>>>(x, gt, Wqkv, bqkv);
    proj_kernel<<<NROWS/128, 256, GEMM_SMEM>>>(Wproj, bproj, out);
}

// round 12
// speedup vs baseline: 1.3325x; 1.2718x over previous
#include <cuda_runtime.h>
#include <cuda_bf16.h>
#include <math.h>
#include <stdint.h>

#define B_   512
#define NW   64
#define NQ   343
#define NTOK 344
#define DIM  96
#define H    3
#define HD   32
#define NROWS (B_*NTOK)
#define XOUT_SZ ((size_t)B_*NQ*DIM)
#define BMSTR 344

typedef unsigned long long u64;

__device__ float g_att[(size_t)B_*NTOK*DIM];
__device__ float g_bm[(size_t)H*NW*NQ*BMSTR + 16];

// ---------------- kernel 0: bm gather (stride 344, col0 = 0) ----------------
__global__ void bm_pre_kernel(const float* __restrict__ btab,
                              const int* __restrict__ ri,
                              const float* __restrict__ mask) {
    size_t gid = (size_t)blockIdx.x * 256 + threadIdx.x;
    if (gid >= (size_t)H*NW*NQ*BMSTR) return;
    int i  = (int)(gid % (NQ*BMSTR));
    int hw = (int)(gid / (NQ*BMSTR));
    int h = hw / NW, w = hw % NW;
    int r = i / BMSTR, j = i % BMSTR;
    float v = 0.f;
    if (j >= 1)
        v = btab[ri[r*NQ + (j-1)]*H + h] + mask[(size_t)w*NQ*NQ + r*NQ + (j-1)];
    g_bm[gid] = v;
}

// ---------------- helpers ----------------
__device__ __forceinline__ uint32_t pack_bf16(float lo, float hi) {
    uint32_t r;
    asm("cvt.rn.bf16x2.f32 %0, %1, %2;" : "=r"(r) : "f"(hi), "f"(lo));
    return r;
}
__device__ __forceinline__ u64 pk2(float lo, float hi) {
    u64 r; asm("mov.b64 %0, {%1, %2};" : "=l"(r) : "f"(lo), "f"(hi)); return r;
}
__device__ __forceinline__ void upk2(float& lo, float& hi, u64 v) {
    asm("mov.b64 {%0, %1}, %2;" : "=f"(lo), "=f"(hi) : "l"(v));
}
__device__ __forceinline__ void fma2(u64& d, u64 a, u64 b) {
    asm("fma.rn.f32x2 %0, %1, %2, %3;" : "=l"(d) : "l"(a), "l"(b), "l"(d));
}

#define MMA_BF16(d, a0,a1,a2,a3, b0,b1)                                      \
    asm volatile("mma.sync.aligned.m16n8k16.row.col.f32.bf16.bf16.f32 "      \
        "{%0,%1,%2,%3},{%4,%5,%6,%7},{%8,%9},{%0,%1,%2,%3};"                 \
        : "+f"(d[0]), "+f"(d[1]), "+f"(d[2]), "+f"(d[3])                      \
        : "r"(a0), "r"(a1), "r"(a2), "r"(a3), "r"(b0), "r"(b1))

// fused smem layout (bytes) — identical to R9
#define SM_XP   0
#define SM_WP   36608
#define SM_BS   56576
#define SM_QS   56960
#define SM_KT   104832
#define SM_VS   150400
#define FUSED_SMEM 201088

__global__ void __launch_bounds__(704, 1)
fused_attn_kernel(const float* __restrict__ x,
                  const float* __restrict__ gt,
                  const float* __restrict__ Wqkv,
                  const float* __restrict__ bqkv) {
    extern __shared__ char smem[];
    uint32_t* Xp = (uint32_t*)(smem + SM_XP);
    uint32_t* Wp = (uint32_t*)(smem + SM_WP);
    float* bis = (float*)(smem + SM_BS);
    float* Qs  = (float*)(smem + SM_QS);
    float* Kt  = (float*)(smem + SM_KT);
    float* Vs  = (float*)(smem + SM_VS);

    const int bid = blockIdx.x;
    const int rep = bid & 7;
    const int hw  = bid >> 3;
    const int w   = hw & 63;
    const int h   = hw >> 6;
    const int b   = (rep << 6) + w;

    const int tid  = threadIdx.x;
    const int wid  = tid >> 5;
    const int lane = tid & 31;
    const int g    = lane >> 2;
    const int tg   = lane & 3;
    const float scale = 0.17677669529663687f;
    const int mb = wid * 16;

    // ---- W and bias fill (once) ----
    for (int idx = tid; idx < 48*96; idx += 704) {
        int k2 = idx / 96, c = idx % 96;
        int row = (c < 32) ? (h*HD + c)
                : (c < 64) ? (DIM + h*HD + (c-32))
                           : (2*DIM + h*HD + (c-64));
        const float* wr = Wqkv + (size_t)row*DIM + 2*k2;
        Wp[k2*104 + c] = pack_bf16(wr[0], wr[1]);
    }
    if (tid < 96) {
        int c = tid;
        int row = (c < 32) ? (h*HD + c)
                : (c < 64) ? (DIM + h*HD + (c-32))
                           : (2*DIM + h*HD + (c-64));
        bis[c] = bqkv[row];
    }

    // ---- phase 1: two-pass bf16 MMA GEMM over k (R9 proven) ----
    float c4[12][4];
    #pragma unroll
    for (int nt = 0; nt < 12; ++nt)
        #pragma unroll
        for (int e = 0; e < 4; ++e) c4[nt][e] = 0.f;

    for (int pass = 0; pass < 2; ++pass) {
        if (pass) __syncthreads();
        for (int idx = tid; idx < 352*24; idx += 704) {
            int n = idx / 24, p = idx % 24;
            float a = 0.f, cc = 0.f;
            if (n < NTOK) {
                const float* src = (n == 0) ? (gt + (size_t)b*DIM)
                                            : (x + ((size_t)b*NQ + (n-1))*DIM);
                float2 v2 = *(const float2*)(src + pass*48 + 2*p);
                a = v2.x; cc = v2.y;
            }
            Xp[n*26 + p] = pack_bf16(a, cc);
        }
        __syncthreads();
        uint32_t xa[3][4];
        #pragma unroll
        for (int kt = 0; kt < 3; ++kt) {
            xa[kt][0] = Xp[(mb+g)*26   + kt*8 + tg];
            xa[kt][1] = Xp[(mb+g+8)*26 + kt*8 + tg];
            xa[kt][2] = Xp[(mb+g)*26   + kt*8 + tg + 4];
            xa[kt][3] = Xp[(mb+g+8)*26 + kt*8 + tg + 4];
        }
        #pragma unroll
        for (int nt = 0; nt < 12; ++nt)
            #pragma unroll
            for (int kt = 0; kt < 3; ++kt) {
                int kr = (pass*3 + kt)*8 + tg;
                uint32_t b0 = Wp[kr*104 + nt*8 + g];
                uint32_t b1 = Wp[(kr+4)*104 + nt*8 + g];
                MMA_BF16(c4[nt], xa[kt][0], xa[kt][1], xa[kt][2], xa[kt][3], b0, b1);
            }
    }
    // epilogue: f32 Q (pair-interleaved) / Kt / V
    #pragma unroll
    for (int nt = 0; nt < 12; ++nt) {
        float bia = bis[nt*8 + 2*tg];
        float bib = bis[nt*8 + 2*tg + 1];
        float v0 = c4[nt][0] + bia, v1 = c4[nt][1] + bib;
        float v2 = c4[nt][2] + bia, v3 = c4[nt][3] + bib;
        const int sec = nt >> 2, ntr = nt & 3;
        const int d0 = ntr*8 + 2*tg;
        const int n1 = mb + g, n2 = n1 + 8;
        if (sec == 0) {
            Qs[(n1>>1)*68 + d0*2     + (n1&1)] = v0*scale;
            Qs[(n1>>1)*68 + (d0+1)*2 + (n1&1)] = v1*scale;
            Qs[(n2>>1)*68 + d0*2     + (n2&1)] = v2*scale;
            Qs[(n2>>1)*68 + (d0+1)*2 + (n2&1)] = v3*scale;
        } else if (sec == 1) {
            Kt[d0*356 + n1] = v0; Kt[(d0+1)*356 + n1] = v1;
            Kt[d0*356 + n2] = v2; Kt[(d0+1)*356 + n2] = v3;
        } else {
            Vs[n1*36 + d0] = v0; Vs[n1*36 + d0 + 1] = v1;
            Vs[n2*36 + d0] = v2; Vs[n2*36 + d0 + 1] = v3;
        }
    }
    __syncthreads();

    // ---- phase 2: f32x2 attention (R9 proven) ----
    const int tq = lane >> 3;
    const int tk = lane & 7;
    u64* Pw = (u64*)(smem + wid*2112);
    const float* bmb = g_bm + ((size_t)(h*NW + w)) * NQ * BMSTR;
    const int q0 = mb + tq*4;
    const int pr0 = tq*2;

    u64 o2[2][4];
    float l4[4] = {0.f, 0.f, 0.f, 0.f};
    #pragma unroll
    for (int p = 0; p < 2; ++p)
        #pragma unroll
        for (int c = 0; c < 4; ++c) o2[p][c] = pk2(0.f, 0.f);

    for (int kb = 0; kb < 11; ++kb) {
        const int kbase = kb*32;

        u64 acc2[2][4];
        #pragma unroll
        for (int p = 0; p < 2; ++p)
            #pragma unroll
            for (int c = 0; c < 4; ++c) acc2[p][c] = pk2(0.f, 0.f);

        const float* kp = Kt + kbase + tk*4;
        const float* qp = Qs + (q0>>1)*68;
        #pragma unroll 8
        for (int d = 0; d < 32; ++d) {
            u64 qa = *(const u64*)(qp + 2*d);
            u64 qb = *(const u64*)(qp + 68 + 2*d);
            float4 kv = *(const float4*)(kp + d*356);
            u64 k20 = pk2(kv.x, kv.x), k21 = pk2(kv.y, kv.y);
            u64 k22 = pk2(kv.z, kv.z), k23 = pk2(kv.w, kv.w);
            fma2(acc2[0][0], qa, k20); fma2(acc2[0][1], qa, k21);
            fma2(acc2[0][2], qa, k22); fma2(acc2[0][3], qa, k23);
            fma2(acc2[1][0], qb, k20); fma2(acc2[1][1], qb, k21);
            fma2(acc2[1][2], qb, k22); fma2(acc2[1][3], qb, k23);
        }

        #pragma unroll
        for (int p = 0; p < 2; ++p) {
            int re = q0 + 2*p, ro = re + 1;
            bool ve = (re >= 1) && (re < NTOK);
            bool vo = (ro < NTOK);
            float4 bme = ve ? __ldg((const float4*)(bmb + (size_t)(re-1)*BMSTR + kbase + tk*4))
                            : make_float4(0.f,0.f,0.f,0.f);
            float4 bmo = vo ? __ldg((const float4*)(bmb + (size_t)(ro-1)*BMSTR + kbase + tk*4))
                            : make_float4(0.f,0.f,0.f,0.f);
            float be[4] = {bme.x, bme.y, bme.z, bme.w};
            float bo[4] = {bmo.x, bmo.y, bmo.z, bmo.w};
            #pragma unroll
            for (int c = 0; c < 4; ++c) {
                float se, so;
                upk2(se, so, acc2[p][c]);
                int j = kbase + tk*4 + c;
                float pe = (j < NTOK) ? __expf(se + be[c]) : 0.f;
                float po = (j < NTOK) ? __expf(so + bo[c]) : 0.f;
                l4[2*p]   += pe;
                l4[2*p+1] += po;
                Pw[(pr0 + p)*33 + tk*4 + c] = pk2(pe, po);
            }
        }
        __syncwarp();

        const float* vp = Vs + (size_t)kbase*36 + tk*4;
        #pragma unroll 8
        for (int j = 0; j < 32; ++j) {
            u64 p20 = Pw[pr0*33 + j];
            u64 p21 = Pw[(pr0+1)*33 + j];
            float4 vv = *(const float4*)(vp + j*36);
            u64 v20 = pk2(vv.x, vv.x), v21 = pk2(vv.y, vv.y);
            u64 v22 = pk2(vv.z, vv.z), v23 = pk2(vv.w, vv.w);
            fma2(o2[0][0], p20, v20); fma2(o2[0][1], p20, v21);
            fma2(o2[0][2], p20, v22); fma2(o2[0][3], p20, v23);
            fma2(o2[1][0], p21, v20); fma2(o2[1][1], p21, v21);
            fma2(o2[1][2], p21, v22); fma2(o2[1][3], p21, v23);
        }
        __syncwarp();
    }

    #pragma unroll
    for (int a = 0; a < 4; ++a) {
        l4[a] += __shfl_xor_sync(0xffffffffu, l4[a], 1);
        l4[a] += __shfl_xor_sync(0xffffffffu, l4[a], 2);
        l4[a] += __shfl_xor_sync(0xffffffffu, l4[a], 4);
    }
    #pragma unroll
    for (int p = 0; p < 2; ++p) {
        float oe[4], oo[4];
        #pragma unroll
        for (int c = 0; c < 4; ++c) upk2(oe[c], oo[c], o2[p][c]);
        int re = q0 + 2*p, ro = re + 1;
        if (re < NTOK) {
            float inv = 1.f / l4[2*p];
            *(float4*)(g_att + ((size_t)b*NTOK + re)*DIM + h*HD + tk*4) =
                make_float4(oe[0]*inv, oe[1]*inv, oe[2]*inv, oe[3]*inv);
        }
        if (ro < NTOK) {
            float inv = 1.f / l4[2*p+1];
            *(float4*)(g_att + ((size_t)b*NTOK + ro)*DIM + h*HD + tk*4) =
                make_float4(oo[0]*inv, oo[1]*inv, oo[2]*inv, oo[3]*inv);
        }
    }
}

// ---------------- proj: f32x2 row-paired, 3 blocks/SM ----------------
// Ai f32 [32 rowpairs][196] = 25088 B, rows interleaved (r0,r1) along k.
// Wsm f32 [96 cols][101]    = 38784 B (stride 101 -> conflict-free col reads).
#define PROJ_SMEM (25088 + 38784)
__global__ void __launch_bounds__(256, 3)
proj_kernel(const float* __restrict__ W,
            const float* __restrict__ bp,
            float* __restrict__ dout) {
    extern __shared__ char psm[];
    float* Ai  = (float*)psm;               // [32][196]
    float* Wsm = (float*)(psm + 25088);     // [96][101]
    const int tid  = threadIdx.x;
    const int row0 = blockIdx.x * 64;
    const int rg = tid >> 5;    // 8 groups of 4 rowpairs
    const int cg = tid & 31;    // 32 groups of 3 cols

    // fill Ai: interleave rows 2rp, 2rp+1 along k
    for (int idx = tid; idx < 32*24; idx += 256) {
        int rp = idx / 24, kq = idx % 24;
        float4 e = *(const float4*)(g_att + (size_t)(row0 + 2*rp)*DIM + 4*kq);
        float4 o = *(const float4*)(g_att + (size_t)(row0 + 2*rp + 1)*DIM + 4*kq);
        *(float4*)&Ai[rp*196 + 8*kq]     = make_float4(e.x, o.x, e.y, o.y);
        *(float4*)&Ai[rp*196 + 8*kq + 4] = make_float4(e.z, o.z, e.w, o.w);
    }
    // fill Wsm [col][k], stride 101
    for (int idx = tid; idx < 96*24; idx += 256) {
        int c = idx / 24, kq = idx % 24;
        float4 wv = *(const float4*)(W + (size_t)c*DIM + 4*kq);
        Wsm[c*101 + 4*kq]     = wv.x;
        Wsm[c*101 + 4*kq + 1] = wv.y;
        Wsm[c*101 + 4*kq + 2] = wv.z;
        Wsm[c*101 + 4*kq + 3] = wv.w;
    }
    __syncthreads();

    u64 a2[4][3];
    #pragma unroll
    for (int i = 0; i < 4; ++i)
        #pragma unroll
        for (int j = 0; j < 3; ++j) a2[i][j] = pk2(0.f, 0.f);

    const float* arow = Ai + rg*4*196;
    const float* wrow = Wsm + cg*3*101;
    #pragma unroll 4
    for (int k = 0; k < 96; ++k) {
        u64 x2[4];
        #pragma unroll
        for (int i = 0; i < 4; ++i)
            x2[i] = *(const u64*)(arow + i*196 + 2*k);
        u64 w0 = pk2(wrow[k],       wrow[k]);
        u64 w1 = pk2(wrow[101 + k], wrow[101 + k]);
        u64 w2 = pk2(wrow[202 + k], wrow[202 + k]);
        #pragma unroll
        for (int i = 0; i < 4; ++i) {
            fma2(a2[i][0], x2[i], w0);
            fma2(a2[i][1], x2[i], w1);
            fma2(a2[i][2], x2[i], w2);
        }
    }

    #pragma unroll
    for (int i = 0; i < 4; ++i) {
        #pragma unroll
        for (int j = 0; j < 3; ++j) {
            float ve, vo;
            upk2(ve, vo, a2[i][j]);
            int c = cg*3 + j;
            float bb = __ldg(bp + c);
            ve += bb; vo += bb;
            int gre = row0 + (rg*4 + i)*2;
            int gro = gre + 1;
            int be_ = gre / NTOK, ne = gre % NTOK;
            int bo_ = gro / NTOK, no = gro % NTOK;
            if (ne == 0) dout[XOUT_SZ + (size_t)be_*DIM + c] = ve;
            else         dout[((size_t)be_*NQ + (ne-1))*DIM + c] = ve;
            if (no == 0) dout[XOUT_SZ + (size_t)bo_*DIM + c] = vo;
            else         dout[((size_t)bo_*NQ + (no-1))*DIM + c] = vo;
        }
    }
}

// ---------------- launch ----------------
extern "C" void kernel_launch(void* const* d_in, const int* in_sizes, int n_in,
                              void* d_out, int out_size) {
    const float* x     = (const float*)d_in[0];
    const float* gt    = (const float*)d_in[1];
    const float* mask  = (const float*)d_in[2];
    const int*   ri    = (const int*)  d_in[3];
    const float* Wqkv  = (const float*)d_in[4];
    const float* bqkv  = (const float*)d_in[5];
    const float* Wproj = (const float*)d_in[6];
    const float* bproj = (const float*)d_in[7];
    const float* btab  = (const float*)d_in[8];
    float* out = (float*)d_out;

    cudaFuncSetAttribute(fused_attn_kernel, cudaFuncAttributeMaxDynamicSharedMemorySize, FUSED_SMEM);
    cudaFuncSetAttribute(proj_kernel,       cudaFuncAttributeMaxDynamicSharedMemorySize, PROJ_SMEM);

    {
        size_t total = (size_t)H*NW*NQ*BMSTR;
        bm_pre_kernel<<<(unsigned)((total + 255)/256), 256>>>(btab, ri, mask);
    }
    fused_attn_kernel<<<B_*H, 704, FUSED_SMEM>>>(x, gt, Wqkv, bqkv);
    proj_kernel<<<NROWS/64, 256, PROJ_SMEM>>>(Wproj, bproj, out);
}

// round 13
// speedup vs baseline: 1.3602x; 1.0208x over previous
#include <cuda_runtime.h>
#include <cuda_bf16.h>
#include <math.h>
#include <stdint.h>

#define B_   512
#define NW   64
#define NQ   343
#define NTOK 344
#define DIM  96
#define H    3
#define HD   32
#define NROWS (B_*NTOK)
#define XOUT_SZ ((size_t)B_*NQ*DIM)
#define BMSTR 344
#define RLN2  1.4426950408889634f

typedef unsigned long long u64;

__device__ float g_att[(size_t)B_*NTOK*DIM];
__device__ float g_bm[(size_t)H*NW*NQ*BMSTR + 16];

// ---------------- kernel 0: bm gather, x4 vectorized, pre-scaled by 1/ln2 ----
__global__ void bm_pre_kernel(const float* __restrict__ btab,
                              const int* __restrict__ ri,
                              const float* __restrict__ mask) {
    size_t gid = (size_t)blockIdx.x * 256 + threadIdx.x;
    if (gid >= (size_t)H*NW*NQ*86) return;
    int q  = (int)(gid % 86);
    size_t t = gid / 86;
    int r  = (int)(t % NQ);
    int hw = (int)(t / NQ);
    int h = hw / NW, w = hw % NW;
    int j0 = q*4;
    const int*   rr = ri + (size_t)r*NQ;
    const float* mr = mask + (size_t)w*NQ*NQ + (size_t)r*NQ;
    float v[4];
    #pragma unroll
    for (int e = 0; e < 4; ++e) {
        int j = j0 + e;
        v[e] = 0.f;
        if (j >= 1)
            v[e] = (btab[rr[j-1]*H + h] + mr[j-1]) * RLN2;
    }
    *(float4*)&g_bm[((size_t)hw*NQ + r)*BMSTR + j0] =
        make_float4(v[0], v[1], v[2], v[3]);
}

// ---------------- helpers ----------------
__device__ __forceinline__ uint32_t pack_bf16(float lo, float hi) {
    uint32_t r;
    asm("cvt.rn.bf16x2.f32 %0, %1, %2;" : "=r"(r) : "f"(hi), "f"(lo));
    return r;
}
__device__ __forceinline__ u64 pk2(float lo, float hi) {
    u64 r; asm("mov.b64 %0, {%1, %2};" : "=l"(r) : "f"(lo), "f"(hi)); return r;
}
__device__ __forceinline__ void upk2(float& lo, float& hi, u64 v) {
    asm("mov.b64 {%0, %1}, %2;" : "=f"(lo), "=f"(hi) : "l"(v));
}
__device__ __forceinline__ void fma2(u64& d, u64 a, u64 b) {
    asm("fma.rn.f32x2 %0, %1, %2, %3;" : "=l"(d) : "l"(a), "l"(b), "l"(d));
}
__device__ __forceinline__ float ex2f(float x) {
    float r; asm("ex2.approx.f32 %0, %1;" : "=f"(r) : "f"(x)); return r;
}

#define MMA_BF16(d, a0,a1,a2,a3, b0,b1)                                      \
    asm volatile("mma.sync.aligned.m16n8k16.row.col.f32.bf16.bf16.f32 "      \
        "{%0,%1,%2,%3},{%4,%5,%6,%7},{%8,%9},{%0,%1,%2,%3};"                 \
        : "+f"(d[0]), "+f"(d[1]), "+f"(d[2]), "+f"(d[3])                      \
        : "r"(a0), "r"(a1), "r"(a2), "r"(a3), "r"(b0), "r"(b1))

// fused smem layout (bytes) — identical to R9/R12
#define SM_XP   0
#define SM_WP   36608
#define SM_BS   56576
#define SM_QS   56960
#define SM_KT   104832
#define SM_VS   150400
#define FUSED_SMEM 201088

__global__ void __launch_bounds__(704, 1)
fused_attn_kernel(const float* __restrict__ x,
                  const float* __restrict__ gt,
                  const float* __restrict__ Wqkv,
                  const float* __restrict__ bqkv) {
    extern __shared__ char smem[];
    uint32_t* Xp = (uint32_t*)(smem + SM_XP);
    uint32_t* Wp = (uint32_t*)(smem + SM_WP);
    float* bis = (float*)(smem + SM_BS);
    float* Qs  = (float*)(smem + SM_QS);
    float* Kt  = (float*)(smem + SM_KT);
    float* Vs  = (float*)(smem + SM_VS);

    const int bid = blockIdx.x;
    const int rep = bid & 7;
    const int hw  = bid >> 3;
    const int w   = hw & 63;
    const int h   = hw >> 6;
    const int b   = (rep << 6) + w;

    const int tid  = threadIdx.x;
    const int wid  = tid >> 5;
    const int lane = tid & 31;
    const int g    = lane >> 2;
    const int tg   = lane & 3;
    const float scale = 0.17677669529663687f * RLN2;   // fold log2(e) into Q
    const int mb = wid * 16;

    // ---- W and bias fill (once) ----
    for (int idx = tid; idx < 48*96; idx += 704) {
        int k2 = idx / 96, c = idx % 96;
        int row = (c < 32) ? (h*HD + c)
                : (c < 64) ? (DIM + h*HD + (c-32))
                           : (2*DIM + h*HD + (c-64));
        const float* wr = Wqkv + (size_t)row*DIM + 2*k2;
        Wp[k2*104 + c] = pack_bf16(wr[0], wr[1]);
    }
    if (tid < 96) {
        int c = tid;
        int row = (c < 32) ? (h*HD + c)
                : (c < 64) ? (DIM + h*HD + (c-32))
                           : (2*DIM + h*HD + (c-64));
        bis[c] = bqkv[row];
    }

    // ---- phase 1: two-pass bf16 MMA GEMM over k ----
    float c4[12][4];
    #pragma unroll
    for (int nt = 0; nt < 12; ++nt)
        #pragma unroll
        for (int e = 0; e < 4; ++e) c4[nt][e] = 0.f;

    for (int pass = 0; pass < 2; ++pass) {
        if (pass) __syncthreads();
        for (int idx = tid; idx < 352*24; idx += 704) {
            int n = idx / 24, p = idx % 24;
            float a = 0.f, cc = 0.f;
            if (n < NTOK) {
                const float* src = (n == 0) ? (gt + (size_t)b*DIM)
                                            : (x + ((size_t)b*NQ + (n-1))*DIM);
                float2 v2 = *(const float2*)(src + pass*48 + 2*p);
                a = v2.x; cc = v2.y;
            }
            Xp[n*26 + p] = pack_bf16(a, cc);
        }
        __syncthreads();
        uint32_t xa[3][4];
        #pragma unroll
        for (int kt = 0; kt < 3; ++kt) {
            xa[kt][0] = Xp[(mb+g)*26   + kt*8 + tg];
            xa[kt][1] = Xp[(mb+g+8)*26 + kt*8 + tg];
            xa[kt][2] = Xp[(mb+g)*26   + kt*8 + tg + 4];
            xa[kt][3] = Xp[(mb+g+8)*26 + kt*8 + tg + 4];
        }
        #pragma unroll
        for (int nt = 0; nt < 12; ++nt)
            #pragma unroll
            for (int kt = 0; kt < 3; ++kt) {
                int kr = (pass*3 + kt)*8 + tg;
                uint32_t b0 = Wp[kr*104 + nt*8 + g];
                uint32_t b1 = Wp[(kr+4)*104 + nt*8 + g];
                MMA_BF16(c4[nt], xa[kt][0], xa[kt][1], xa[kt][2], xa[kt][3], b0, b1);
            }
    }
    // epilogue: f32 Q (pair-interleaved, pre-scaled) / Kt / V
    #pragma unroll
    for (int nt = 0; nt < 12; ++nt) {
        float bia = bis[nt*8 + 2*tg];
        float bib = bis[nt*8 + 2*tg + 1];
        float v0 = c4[nt][0] + bia, v1 = c4[nt][1] + bib;
        float v2 = c4[nt][2] + bia, v3 = c4[nt][3] + bib;
        const int sec = nt >> 2, ntr = nt & 3;
        const int d0 = ntr*8 + 2*tg;
        const int n1 = mb + g, n2 = n1 + 8;
        if (sec == 0) {
            Qs[(n1>>1)*68 + d0*2     + (n1&1)] = v0*scale;
            Qs[(n1>>1)*68 + (d0+1)*2 + (n1&1)] = v1*scale;
            Qs[(n2>>1)*68 + d0*2     + (n2&1)] = v2*scale;
            Qs[(n2>>1)*68 + (d0+1)*2 + (n2&1)] = v3*scale;
        } else if (sec == 1) {
            Kt[d0*356 + n1] = v0; Kt[(d0+1)*356 + n1] = v1;
            Kt[d0*356 + n2] = v2; Kt[(d0+1)*356 + n2] = v3;
        } else {
            Vs[n1*36 + d0] = v0; Vs[n1*36 + d0 + 1] = v1;
            Vs[n2*36 + d0] = v2; Vs[n2*36 + d0 + 1] = v3;
        }
    }
    __syncthreads();

    // ---- phase 2: f32x2 attention with bm prefetch + ex2 ----
    const int tq = lane >> 3;
    const int tk = lane & 7;
    u64* Pw = (u64*)(smem + wid*2112);
    const float* bmb = g_bm + ((size_t)(h*NW + w)) * NQ * BMSTR;
    const int q0 = mb + tq*4;
    const int pr0 = tq*2;

    u64 o2[2][4];
    float l4[4] = {0.f, 0.f, 0.f, 0.f};
    #pragma unroll
    for (int p = 0; p < 2; ++p)
        #pragma unroll
        for (int c = 0; c < 4; ++c) o2[p][c] = pk2(0.f, 0.f);

    for (int kb = 0; kb < 11; ++kb) {
        const int kbase = kb*32;

        // ---- prefetch bm for THIS kb before the QK loop (hide L2 latency) ----
        float4 bmv[2][2];
        #pragma unroll
        for (int p = 0; p < 2; ++p) {
            int re = q0 + 2*p, ro = re + 1;
            bool ve = (re >= 1) && (re < NTOK);
            bool vo = (ro < NTOK);
            bmv[p][0] = ve ? __ldg((const float4*)(bmb + (size_t)(re-1)*BMSTR + kbase + tk*4))
                           : make_float4(0.f,0.f,0.f,0.f);
            bmv[p][1] = vo ? __ldg((const float4*)(bmb + (size_t)(ro-1)*BMSTR + kbase + tk*4))
                           : make_float4(0.f,0.f,0.f,0.f);
        }

        // ---- S = Q K^T ----
        u64 acc2[2][4];
        #pragma unroll
        for (int p = 0; p < 2; ++p)
            #pragma unroll
            for (int c = 0; c < 4; ++c) acc2[p][c] = pk2(0.f, 0.f);

        const float* kp = Kt + kbase + tk*4;
        const float* qp = Qs + (q0>>1)*68;
        #pragma unroll 8
        for (int d = 0; d < 32; ++d) {
            u64 qa = *(const u64*)(qp + 2*d);
            u64 qb = *(const u64*)(qp + 68 + 2*d);
            float4 kv = *(const float4*)(kp + d*356);
            u64 k20 = pk2(kv.x, kv.x), k21 = pk2(kv.y, kv.y);
            u64 k22 = pk2(kv.z, kv.z), k23 = pk2(kv.w, kv.w);
            fma2(acc2[0][0], qa, k20); fma2(acc2[0][1], qa, k21);
            fma2(acc2[0][2], qa, k22); fma2(acc2[0][3], qa, k23);
            fma2(acc2[1][0], qb, k20); fma2(acc2[1][1], qb, k21);
            fma2(acc2[1][2], qb, k22); fma2(acc2[1][3], qb, k23);
        }

        // ---- exp2 (logits pre-scaled by log2 e) ----
        #pragma unroll
        for (int p = 0; p < 2; ++p) {
            float be[4] = {bmv[p][0].x, bmv[p][0].y, bmv[p][0].z, bmv[p][0].w};
            float bo[4] = {bmv[p][1].x, bmv[p][1].y, bmv[p][1].z, bmv[p][1].w};
            #pragma unroll
            for (int c = 0; c < 4; ++c) {
                float se, so;
                upk2(se, so, acc2[p][c]);
                int j = kbase + tk*4 + c;
                float pe = (j < NTOK) ? ex2f(se + be[c]) : 0.f;
                float po = (j < NTOK) ? ex2f(so + bo[c]) : 0.f;
                l4[2*p]   += pe;
                l4[2*p+1] += po;
                Pw[(pr0 + p)*33 + tk*4 + c] = pk2(pe, po);
            }
        }
        __syncwarp();

        // ---- O += P V ----
        const float* vp = Vs + (size_t)kbase*36 + tk*4;
        #pragma unroll 8
        for (int j = 0; j < 32; ++j) {
            u64 p20 = Pw[pr0*33 + j];
            u64 p21 = Pw[(pr0+1)*33 + j];
            float4 vv = *(const float4*)(vp + j*36);
            u64 v20 = pk2(vv.x, vv.x), v21 = pk2(vv.y, vv.y);
            u64 v22 = pk2(vv.z, vv.z), v23 = pk2(vv.w, vv.w);
            fma2(o2[0][0], p20, v20); fma2(o2[0][1], p20, v21);
            fma2(o2[0][2], p20, v22); fma2(o2[0][3], p20, v23);
            fma2(o2[1][0], p21, v20); fma2(o2[1][1], p21, v21);
            fma2(o2[1][2], p21, v22); fma2(o2[1][3], p21, v23);
        }
        __syncwarp();
    }

    #pragma unroll
    for (int a = 0; a < 4; ++a) {
        l4[a] += __shfl_xor_sync(0xffffffffu, l4[a], 1);
        l4[a] += __shfl_xor_sync(0xffffffffu, l4[a], 2);
        l4[a] += __shfl_xor_sync(0xffffffffu, l4[a], 4);
    }
    #pragma unroll
    for (int p = 0; p < 2; ++p) {
        float oe[4], oo[4];
        #pragma unroll
        for (int c = 0; c < 4; ++c) upk2(oe[c], oo[c], o2[p][c]);
        int re = q0 + 2*p, ro = re + 1;
        if (re < NTOK) {
            float inv = 1.f / l4[2*p];
            *(float4*)(g_att + ((size_t)b*NTOK + re)*DIM + h*HD + tk*4) =
                make_float4(oe[0]*inv, oe[1]*inv, oe[2]*inv, oe[3]*inv);
        }
        if (ro < NTOK) {
            float inv = 1.f / l4[2*p+1];
            *(float4*)(g_att + ((size_t)b*NTOK + ro)*DIM + h*HD + tk*4) =
                make_float4(oo[0]*inv, oo[1]*inv, oo[2]*inv, oo[3]*inv);
        }
    }
}

// ---------------- proj: R12 proven f32x2 version (unchanged) ----------------
#define PROJ_SMEM (25088 + 38784)
__global__ void __launch_bounds__(256, 3)
proj_kernel(const float* __restrict__ W,
            const float* __restrict__ bp,
            float* __restrict__ dout) {
    extern __shared__ char psm[];
    float* Ai  = (float*)psm;               // [32][196]
    float* Wsm = (float*)(psm + 25088);     // [96][101]
    const int tid  = threadIdx.x;
    const int row0 = blockIdx.x * 64;
    const int rg = tid >> 5;
    const int cg = tid & 31;

    for (int idx = tid; idx < 32*24; idx += 256) {
        int rp = idx / 24, kq = idx % 24;
        float4 e = *(const float4*)(g_att + (size_t)(row0 + 2*rp)*DIM + 4*kq);
        float4 o = *(const float4*)(g_att + (size_t)(row0 + 2*rp + 1)*DIM + 4*kq);
        *(float4*)&Ai[rp*196 + 8*kq]     = make_float4(e.x, o.x, e.y, o.y);
        *(float4*)&Ai[rp*196 + 8*kq + 4] = make_float4(e.z, o.z, e.w, o.w);
    }
    for (int idx = tid; idx < 96*24; idx += 256) {
        int c = idx / 24, kq = idx % 24;
        float4 wv = *(const float4*)(W + (size_t)c*DIM + 4*kq);
        Wsm[c*101 + 4*kq]     = wv.x;
        Wsm[c*101 + 4*kq + 1] = wv.y;
        Wsm[c*101 + 4*kq + 2] = wv.z;
        Wsm[c*101 + 4*kq + 3] = wv.w;
    }
    __syncthreads();

    u64 a2[4][3];
    #pragma unroll
    for (int i = 0; i < 4; ++i)
        #pragma unroll
        for (int j = 0; j < 3; ++j) a2[i][j] = pk2(0.f, 0.f);

    const float* arow = Ai + rg*4*196;
    const float* wrow = Wsm + cg*3*101;
    #pragma unroll 4
    for (int k = 0; k < 96; ++k) {
        u64 x2[4];
        #pragma unroll
        for (int i = 0; i < 4; ++i)
            x2[i] = *(const u64*)(arow + i*196 + 2*k);
        u64 w0 = pk2(wrow[k],       wrow[k]);
        u64 w1 = pk2(wrow[101 + k], wrow[101 + k]);
        u64 w2 = pk2(wrow[202 + k], wrow[202 + k]);
        #pragma unroll
        for (int i = 0; i < 4; ++i) {
            fma2(a2[i][0], x2[i], w0);
            fma2(a2[i][1], x2[i], w1);
            fma2(a2[i][2], x2[i], w2);
        }
    }

    #pragma unroll
    for (int i = 0; i < 4; ++i) {
        #pragma unroll
        for (int j = 0; j < 3; ++j) {
            float ve, vo;
            upk2(ve, vo, a2[i][j]);
            int c = cg*3 + j;
            float bb = __ldg(bp + c);
            ve += bb; vo += bb;
            int gre = row0 + (rg*4 + i)*2;
            int gro = gre + 1;
            int be_ = gre / NTOK, ne = gre % NTOK;
            int bo_ = gro / NTOK, no = gro % NTOK;
            if (ne == 0) dout[XOUT_SZ + (size_t)be_*DIM + c] = ve;
            else         dout[((size_t)be_*NQ + (ne-1))*DIM + c] = ve;
            if (no == 0) dout[XOUT_SZ + (size_t)bo_*DIM + c] = vo;
            else         dout[((size_t)bo_*NQ + (no-1))*DIM + c] = vo;
        }
    }
}

// ---------------- launch ----------------
extern "C" void kernel_launch(void* const* d_in, const int* in_sizes, int n_in,
                              void* d_out, int out_size) {
    const float* x     = (const float*)d_in[0];
    const float* gt    = (const float*)d_in[1];
    const float* mask  = (const float*)d_in[2];
    const int*   ri    = (const int*)  d_in[3];
    const float* Wqkv  = (const float*)d_in[4];
    const float* bqkv  = (const float*)d_in[5];
    const float* Wproj = (const float*)d_in[6];
    const float* bproj = (const float*)d_in[7];
    const float* btab  = (const float*)d_in[8];
    float* out = (float*)d_out;

    cudaFuncSetAttribute(fused_attn_kernel, cudaFuncAttributeMaxDynamicSharedMemorySize, FUSED_SMEM);
    cudaFuncSetAttribute(proj_kernel,       cudaFuncAttributeMaxDynamicSharedMemorySize, PROJ_SMEM);

    {
        size_t total = (size_t)H*NW*NQ*86;
        bm_pre_kernel<<<(unsigned)((total + 255)/256), 256>>>(btab, ri, mask);
    }
    fused_attn_kernel<<<B_*H, 704, FUSED_SMEM>>>(x, gt, Wqkv, bqkv);
    proj_kernel<<<NROWS/64, 256, PROJ_SMEM>>>(Wproj, bproj, out);
}